// round 1
// baseline (speedup 1.0000x reference)
#include <cuda_runtime.h>
#include <cuda_fp16.h>
#include <stdint.h>
#include <math.h>

// Problem constants
#define H_DIM  2048
#define E_NUM  16
#define F_DIM  1408
#define FS_DIM 4096
#define T_NUM  2048   // B*S = 2*1024
#define TOPK   4
#define CAP    2048   // worst-case tokens per expert

// SMEM strides (halves). 40 -> conflict-free half2 fragment loads.
#define AS_STR 40
#define BS_STR 40

// ---------------- scratch (static device memory; no allocation at runtime) ---
__device__ __half d_Xg[(size_t)E_NUM * CAP * H_DIM];   // gathered, w-scaled tokens (fp16)
__device__ __half d_xh[(size_t)T_NUM * H_DIM];         // fp16 copy of x (shared expert A)
__device__ __half d_hr[(size_t)E_NUM * CAP * F_DIM];   // routed h = silu(g)*u
__device__ __half d_hs[(size_t)T_NUM * FS_DIM];        // shared h
__device__ int    d_cnt[E_NUM];
__device__ int    d_perm[E_NUM * CAP];                 // slot -> token
__device__ float  d_wslot[E_NUM * CAP];                // slot -> routing weight

// ---------------- helpers ----------------------------------------------------
__device__ __forceinline__ void mma16816(float* c, const uint32_t* a, const uint32_t* b) {
    asm volatile(
        "mma.sync.aligned.m16n8k16.row.col.f32.f16.f16.f32 "
        "{%0,%1,%2,%3}, {%4,%5,%6,%7}, {%8,%9}, {%0,%1,%2,%3};\n"
        : "+f"(c[0]), "+f"(c[1]), "+f"(c[2]), "+f"(c[3])
        : "r"(a[0]), "r"(a[1]), "r"(a[2]), "r"(a[3]), "r"(b[0]), "r"(b[1]));
}

__device__ __forceinline__ float silu_f(float g) {
    return g / (1.0f + expf(-g));
}

// ---------------- kernel 0: zero expert counters -----------------------------
__global__ void moe_zero_cnt_kernel(int* cnt) {
    if (threadIdx.x < E_NUM) cnt[threadIdx.x] = 0;
}

// ---------------- kernel 1: router + softmax + top4 + gather -----------------
// one block (128 threads) per token
__global__ void moe_router_kernel(const float* __restrict__ x,
                                  const float* __restrict__ wr,
                                  __half* __restrict__ xh,
                                  __half* __restrict__ Xg,
                                  int* __restrict__ cnt,
                                  int* __restrict__ perm,
                                  float* __restrict__ wslot) {
    __shared__ float xs[H_DIM];
    __shared__ float logits[E_NUM];
    __shared__ int   sel_slot[TOPK];
    __shared__ float sel_w[TOPK];

    const int t = blockIdx.x;
    const int tid = threadIdx.x;
    const int lane = tid & 31;
    const int warp = tid >> 5;

    // load token row into smem
    for (int i = tid; i < H_DIM; i += 128) xs[i] = x[(size_t)t * H_DIM + i];
    __syncthreads();

    // 4 warps x 4 experts each: dot products
    for (int e = warp * 4; e < warp * 4 + 4; e++) {
        float s = 0.f;
        const float* wre = wr + (size_t)e * H_DIM;
        for (int h = lane; h < H_DIM; h += 32) s += xs[h] * wre[h];
        #pragma unroll
        for (int off = 16; off; off >>= 1) s += __shfl_xor_sync(0xffffffffu, s, off);
        if (lane == 0) logits[e] = s;
    }
    __syncthreads();

    if (tid == 0) {
        float p[E_NUM];
        float mx = -1e30f;
        #pragma unroll
        for (int e = 0; e < E_NUM; e++) mx = fmaxf(mx, logits[e]);
        #pragma unroll
        for (int e = 0; e < E_NUM; e++) p[e] = expf(logits[e] - mx);
        // top-4 (selection; ties -> lower index, same as jax top_k)
        int   se[TOPK];
        float sw[TOPK];
        float tw = 0.f;
        for (int j = 0; j < TOPK; j++) {
            int am = 0; float bv = -1.f;
            #pragma unroll
            for (int e = 0; e < E_NUM; e++) { if (p[e] > bv) { bv = p[e]; am = e; } }
            se[j] = am; sw[j] = bv; tw += bv; p[am] = -2.f;
        }
        float inv = 1.f / tw;
        for (int j = 0; j < TOPK; j++) {
            float w = sw[j] * inv;
            int pos = atomicAdd(&cnt[se[j]], 1);
            int slot = se[j] * CAP + pos;
            perm[slot]  = t;
            wslot[slot] = w;
            sel_slot[j] = slot;
            sel_w[j]    = w;
        }
    }
    __syncthreads();

    // write fp16 copies: xh (unscaled) and 4 scaled gathered rows
    const int s0 = sel_slot[0], s1 = sel_slot[1], s2 = sel_slot[2], s3 = sel_slot[3];
    const float w0 = sel_w[0], w1 = sel_w[1], w2 = sel_w[2], w3 = sel_w[3];
    for (int i = tid; i < H_DIM; i += 128) {
        float v = xs[i];
        xh[(size_t)t * H_DIM + i]  = __float2half(v);
        Xg[(size_t)s0 * H_DIM + i] = __float2half(w0 * v);
        Xg[(size_t)s1 * H_DIM + i] = __float2half(w1 * v);
        Xg[(size_t)s2 * H_DIM + i] = __float2half(w2 * v);
        Xg[(size_t)s3 * H_DIM + i] = __float2half(w3 * v);
    }
}

// ---------------- kernel 2: fused gate/up GEMM + silu ------------------------
// C tile 128x64, K = H_DIM, BK=32, 256 threads (8 warps: 4m x 2n, warp 32x32)
// h[m][n] = silu(A@Wg) * (A@Wu), written fp16
template <bool ROUTED>
__global__ __launch_bounds__(256)
void moe_gu_kernel(const __half* __restrict__ Abase,
                   const float* __restrict__ WgAll,
                   const float* __restrict__ WuAll,
                   __half* __restrict__ Hbase,
                   const int* __restrict__ cnt,
                   int F) {
    const int e = blockIdx.z;
    int M;
    const __half* A;
    const float *Wg, *Wu;
    __half* Hout;
    if (ROUTED) {
        M = cnt[e];
        A    = Abase + (size_t)e * CAP * H_DIM;
        Wg   = WgAll + (size_t)e * H_DIM * F;
        Wu   = WuAll + (size_t)e * H_DIM * F;
        Hout = Hbase + (size_t)e * CAP * F;
    } else {
        M = T_NUM; A = Abase; Wg = WgAll; Wu = WuAll; Hout = Hbase;
    }
    const int m0 = blockIdx.x * 128;
    if (m0 >= M) return;
    const int n0 = blockIdx.y * 64;

    __shared__ alignas(16) __half As[128 * AS_STR];
    __shared__ alignas(16) __half Bgs[64 * BS_STR];
    __shared__ alignas(16) __half Bus[64 * BS_STR];

    const int tid = threadIdx.x;
    const int lane = tid & 31;
    const int warp = tid >> 5;
    const int wm = warp >> 1, wn = warp & 1;

    float accg[2][4][4], accu[2][4][4];
    #pragma unroll
    for (int a = 0; a < 2; a++)
        #pragma unroll
        for (int b = 0; b < 4; b++)
            #pragma unroll
            for (int c = 0; c < 4; c++) { accg[a][b][c] = 0.f; accu[a][b][c] = 0.f; }

    const __half2 hz = __floats2half2_rn(0.f, 0.f);

    for (int k0 = 0; k0 < H_DIM; k0 += 32) {
        // A tile: 128 x 32 halves (half2 granularity)
        for (int i = tid; i < 128 * 16; i += 256) {
            int row = i >> 4, c2 = i & 15;
            int gr = m0 + row;
            __half2 v = hz;
            if (gr < M) v = *(const __half2*)&A[(size_t)gr * H_DIM + k0 + c2 * 2];
            *(__half2*)&As[row * AS_STR + c2 * 2] = v;
        }
        // B tiles: 32(k) x 64(n) each, fp32->fp16, stored [n][k]
        for (int i = tid; i < 32 * 64; i += 256) {
            int kk = i >> 6, n = i & 63;
            size_t gidx = (size_t)(k0 + kk) * F + n0 + n;
            Bgs[n * BS_STR + kk] = __float2half(Wg[gidx]);
            Bus[n * BS_STR + kk] = __float2half(Wu[gidx]);
        }
        __syncthreads();

        #pragma unroll
        for (int kk = 0; kk < 32; kk += 16) {
            uint32_t a[2][4];
            #pragma unroll
            for (int mf = 0; mf < 2; mf++) {
                int row = wm * 32 + mf * 16 + (lane >> 2);
                int col = kk + (lane & 3) * 2;
                const __half* base = &As[row * AS_STR + col];
                a[mf][0] = *(const uint32_t*)(base);
                a[mf][1] = *(const uint32_t*)(base + 8 * AS_STR);
                a[mf][2] = *(const uint32_t*)(base + 8);
                a[mf][3] = *(const uint32_t*)(base + 8 * AS_STR + 8);
            }
            #pragma unroll
            for (int nf = 0; nf < 4; nf++) {
                int n = wn * 32 + nf * 8 + (lane >> 2);
                int c = kk + (lane & 3) * 2;
                uint32_t bg[2], bu[2];
                bg[0] = *(const uint32_t*)&Bgs[n * BS_STR + c];
                bg[1] = *(const uint32_t*)&Bgs[n * BS_STR + c + 8];
                bu[0] = *(const uint32_t*)&Bus[n * BS_STR + c];
                bu[1] = *(const uint32_t*)&Bus[n * BS_STR + c + 8];
                #pragma unroll
                for (int mf = 0; mf < 2; mf++) {
                    mma16816(accg[mf][nf], a[mf], bg);
                    mma16816(accu[mf][nf], a[mf], bu);
                }
            }
        }
        __syncthreads();
    }

    // epilogue: h = silu(g) * u -> fp16
    #pragma unroll
    for (int mf = 0; mf < 2; mf++) {
        #pragma unroll
        for (int nf = 0; nf < 4; nf++) {
            int row0 = m0 + wm * 32 + mf * 16 + (lane >> 2);
            int col  = n0 + wn * 32 + nf * 8 + (lane & 3) * 2;
            float* g = accg[mf][nf];
            float* u = accu[mf][nf];
            if (row0 < M) {
                float h0 = silu_f(g[0]) * u[0];
                float h1 = silu_f(g[1]) * u[1];
                *(__half2*)&Hout[(size_t)row0 * F + col] = __floats2half2_rn(h0, h1);
            }
            int row1 = row0 + 8;
            if (row1 < M) {
                float h2 = silu_f(g[2]) * u[2];
                float h3 = silu_f(g[3]) * u[3];
                *(__half2*)&Hout[(size_t)row1 * F + col] = __floats2half2_rn(h2, h3);
            }
        }
    }
}

// ---------------- kernel 3: down GEMM ----------------------------------------
// C tile 128x64 over N=H_DIM, K = F (1408) or FS (4096)
// ROUTED: atomicAdd w * y into out rows by token; else direct store (initializes out)
template <bool ROUTED>
__global__ __launch_bounds__(256)
void moe_down_kernel(const __half* __restrict__ Hbase,
                     const float* __restrict__ WdAll,
                     float* __restrict__ out,
                     const int* __restrict__ cnt,
                     const int* __restrict__ perm,
                     const float* __restrict__ wslot,
                     int K) {
    const int e = blockIdx.z;
    int M;
    const __half* A;
    const float* Wd;
    if (ROUTED) {
        M  = cnt[e];
        A  = Hbase + (size_t)e * CAP * K;
        Wd = WdAll + (size_t)e * K * H_DIM;
    } else {
        M = T_NUM; A = Hbase; Wd = WdAll;
    }
    const int m0 = blockIdx.x * 128;
    if (m0 >= M) return;
    const int n0 = blockIdx.y * 64;

    __shared__ alignas(16) __half As[128 * AS_STR];
    __shared__ alignas(16) __half Bs[64 * BS_STR];

    const int tid = threadIdx.x;
    const int lane = tid & 31;
    const int warp = tid >> 5;
    const int wm = warp >> 1, wn = warp & 1;

    float acc[2][4][4];
    #pragma unroll
    for (int a = 0; a < 2; a++)
        #pragma unroll
        for (int b = 0; b < 4; b++)
            #pragma unroll
            for (int c = 0; c < 4; c++) acc[a][b][c] = 0.f;

    const __half2 hz = __floats2half2_rn(0.f, 0.f);

    for (int k0 = 0; k0 < K; k0 += 32) {
        for (int i = tid; i < 128 * 16; i += 256) {
            int row = i >> 4, c2 = i & 15;
            int gr = m0 + row;
            __half2 v = hz;
            if (gr < M) v = *(const __half2*)&A[(size_t)gr * K + k0 + c2 * 2];
            *(__half2*)&As[row * AS_STR + c2 * 2] = v;
        }
        for (int i = tid; i < 32 * 64; i += 256) {
            int kk = i >> 6, n = i & 63;
            Bs[n * BS_STR + kk] = __float2half(Wd[(size_t)(k0 + kk) * H_DIM + n0 + n]);
        }
        __syncthreads();

        #pragma unroll
        for (int kk = 0; kk < 32; kk += 16) {
            uint32_t a[2][4];
            #pragma unroll
            for (int mf = 0; mf < 2; mf++) {
                int row = wm * 32 + mf * 16 + (lane >> 2);
                int col = kk + (lane & 3) * 2;
                const __half* base = &As[row * AS_STR + col];
                a[mf][0] = *(const uint32_t*)(base);
                a[mf][1] = *(const uint32_t*)(base + 8 * AS_STR);
                a[mf][2] = *(const uint32_t*)(base + 8);
                a[mf][3] = *(const uint32_t*)(base + 8 * AS_STR + 8);
            }
            #pragma unroll
            for (int nf = 0; nf < 4; nf++) {
                int n = wn * 32 + nf * 8 + (lane >> 2);
                int c = kk + (lane & 3) * 2;
                uint32_t b[2];
                b[0] = *(const uint32_t*)&Bs[n * BS_STR + c];
                b[1] = *(const uint32_t*)&Bs[n * BS_STR + c + 8];
                #pragma unroll
                for (int mf = 0; mf < 2; mf++) mma16816(acc[mf][nf], a[mf], b);
            }
        }
        __syncthreads();
    }

    // epilogue
    #pragma unroll
    for (int mf = 0; mf < 2; mf++) {
        #pragma unroll
        for (int nf = 0; nf < 4; nf++) {
            int row0 = m0 + wm * 32 + mf * 16 + (lane >> 2);
            int col  = n0 + wn * 32 + nf * 8 + (lane & 3) * 2;
            float* c = acc[mf][nf];
            if (ROUTED) {
                if (row0 < M) {
                    int slot = e * CAP + row0;
                    int t = perm[slot]; float w = wslot[slot];
                    atomicAdd(&out[(size_t)t * H_DIM + col],     w * c[0]);
                    atomicAdd(&out[(size_t)t * H_DIM + col + 1], w * c[1]);
                }
                int row1 = row0 + 8;
                if (row1 < M) {
                    int slot = e * CAP + row1;
                    int t = perm[slot]; float w = wslot[slot];
                    atomicAdd(&out[(size_t)t * H_DIM + col],     w * c[2]);
                    atomicAdd(&out[(size_t)t * H_DIM + col + 1], w * c[3]);
                }
            } else {
                out[(size_t)row0 * H_DIM + col]     = c[0];
                out[(size_t)row0 * H_DIM + col + 1] = c[1];
                out[(size_t)(row0 + 8) * H_DIM + col]     = c[2];
                out[(size_t)(row0 + 8) * H_DIM + col + 1] = c[3];
            }
        }
    }
}

// ---------------- launch -----------------------------------------------------
extern "C" void kernel_launch(void* const* d_in, const int* in_sizes, int n_in,
                              void* d_out, int out_size) {
    const float* x   = (const float*)d_in[0];
    const float* wr  = (const float*)d_in[1];
    const float* Wg  = (const float*)d_in[2];
    const float* Wu  = (const float*)d_in[3];
    const float* Wd  = (const float*)d_in[4];
    const float* Wgs = (const float*)d_in[5];
    const float* Wus = (const float*)d_in[6];
    const float* Wds = (const float*)d_in[7];
    float* out = (float*)d_out;

    __half *Xg, *xh, *hr, *hs;
    int *cnt, *perm;
    float *wslot;
    cudaGetSymbolAddress((void**)&Xg,    d_Xg);
    cudaGetSymbolAddress((void**)&xh,    d_xh);
    cudaGetSymbolAddress((void**)&hr,    d_hr);
    cudaGetSymbolAddress((void**)&hs,    d_hs);
    cudaGetSymbolAddress((void**)&cnt,   d_cnt);
    cudaGetSymbolAddress((void**)&perm,  d_perm);
    cudaGetSymbolAddress((void**)&wslot, d_wslot);

    moe_zero_cnt_kernel<<<1, 32>>>(cnt);
    moe_router_kernel<<<T_NUM, 128>>>(x, wr, xh, Xg, cnt, perm, wslot);

    // routed gate/up: grid (m-tiles up to CAP/128, F/64 n-tiles, E experts)
    moe_gu_kernel<true><<<dim3(CAP / 128, F_DIM / 64, E_NUM), 256>>>(Xg, Wg, Wu, hr, cnt, F_DIM);
    // shared gate/up
    moe_gu_kernel<false><<<dim3(T_NUM / 128, FS_DIM / 64, 1), 256>>>(xh, Wgs, Wus, hs, nullptr, FS_DIM);

    // shared down first (direct stores initialize every out element)
    moe_down_kernel<false><<<dim3(T_NUM / 128, H_DIM / 64, 1), 256>>>(hs, Wds, out, nullptr, nullptr, nullptr, FS_DIM);
    // routed down: atomic accumulate
    moe_down_kernel<true><<<dim3(CAP / 128, H_DIM / 64, E_NUM), 256>>>(hr, Wd, out, cnt, perm, wslot, F_DIM);
}

// round 2
// speedup vs baseline: 2.4800x; 2.4800x over previous
#include <cuda_runtime.h>
#include <cuda_fp16.h>
#include <stdint.h>
#include <math.h>

// ---------------- problem constants ------------------------------------------
#define H_DIM  2048
#define E_NUM  16
#define F_DIM  1408
#define FS_DIM 4096
#define T_NUM  2048   // B*S
#define TOPK   4
#define CAP    2048

// ---------------- GEMM tiling ------------------------------------------------
#define BM 128
#define BN 64
#define BK 64
#define STAGES 3
#define KSTR 72                    // smem row stride (halves): 144B, conflict-free
#define A_HALVES (BM * KSTR)       // 9216
#define B_HALVES (BN * KSTR)       // 4608
#define GU_STAGE_H (A_HALVES + 2 * B_HALVES)
#define DN_STAGE_H (A_HALVES + B_HALVES)
#define GU_SMEM (GU_STAGE_H * STAGES * 2)   // 110592 B
#define DN_SMEM (DN_STAGE_H * STAGES * 2)   // 82944 B

// ---------------- static scratch ---------------------------------------------
__device__ __half d_Xg[(size_t)E_NUM * CAP * H_DIM];    // gathered w*x (fp16)
__device__ __half d_xh[(size_t)T_NUM * H_DIM];          // fp16 x (shared expert)
__device__ __half d_hr[(size_t)E_NUM * CAP * F_DIM];    // routed h
__device__ __half d_hs[(size_t)T_NUM * FS_DIM];         // shared h
__device__ float  d_Yr[(size_t)E_NUM * CAP * H_DIM];    // routed down output per slot
__device__ __half d_WgT[(size_t)E_NUM * H_DIM * F_DIM]; // [e][F][H] fp16
__device__ __half d_WuT[(size_t)E_NUM * H_DIM * F_DIM];
__device__ __half d_WdT[(size_t)E_NUM * H_DIM * F_DIM]; // [e][H][F]
__device__ __half d_WgsT[(size_t)H_DIM * FS_DIM];       // [FS][H]
__device__ __half d_WusT[(size_t)H_DIM * FS_DIM];
__device__ __half d_WdsT[(size_t)H_DIM * FS_DIM];       // [H][FS]
__device__ int    d_cnt[E_NUM];
__device__ int    d_t2s[T_NUM * TOPK];
__device__ float  d_t2w[T_NUM * TOPK];

// ---------------- helpers ----------------------------------------------------
__device__ __forceinline__ uint32_t sptr(const void* p) {
    return (uint32_t)__cvta_generic_to_shared(p);
}
__device__ __forceinline__ void cp16(uint32_t dst, const void* src) {
    asm volatile("cp.async.cg.shared.global [%0], [%1], 16;\n" :: "r"(dst), "l"(src));
}
__device__ __forceinline__ void cp16z(uint32_t dst, const void* src, bool pred) {
    int sz = pred ? 16 : 0;
    asm volatile("cp.async.cg.shared.global [%0], [%1], 16, %2;\n" :: "r"(dst), "l"(src), "r"(sz));
}
#define CP_COMMIT asm volatile("cp.async.commit_group;\n" ::: "memory")
#define CP_WAIT1  asm volatile("cp.async.wait_group 1;\n" ::: "memory")

__device__ __forceinline__ void ldm_x4(uint32_t* r, uint32_t addr) {
    asm volatile("ldmatrix.sync.aligned.m8n8.x4.shared.b16 {%0,%1,%2,%3}, [%4];\n"
                 : "=r"(r[0]), "=r"(r[1]), "=r"(r[2]), "=r"(r[3]) : "r"(addr));
}
__device__ __forceinline__ void mma16816(float* c, const uint32_t* a, const uint32_t* b) {
    asm volatile(
        "mma.sync.aligned.m16n8k16.row.col.f32.f16.f16.f32 "
        "{%0,%1,%2,%3}, {%4,%5,%6,%7}, {%8,%9}, {%0,%1,%2,%3};\n"
        : "+f"(c[0]), "+f"(c[1]), "+f"(c[2]), "+f"(c[3])
        : "r"(a[0]), "r"(a[1]), "r"(a[2]), "r"(a[3]), "r"(b[0]), "r"(b[1]));
}
__device__ __forceinline__ float silu_f(float g) {
    return g / (1.0f + __expf(-g));
}

// ---------------- kernel: fp32 [K][N] -> fp16 [N][K] transpose (per batch z) --
__global__ void transpose_f2h_kernel(const float* __restrict__ in,
                                     __half* __restrict__ out, int K, int N) {
    __shared__ float tile[32][33];
    const float* inb = in + (size_t)blockIdx.z * K * N;
    __half* outb = out + (size_t)blockIdx.z * K * N;
    int n0 = blockIdx.x * 32, k0 = blockIdx.y * 32;
    int tx = threadIdx.x, ty = threadIdx.y;
    #pragma unroll
    for (int i = 0; i < 4; i++)
        tile[ty + 8 * i][tx] = inb[(size_t)(k0 + ty + 8 * i) * N + n0 + tx];
    __syncthreads();
    #pragma unroll
    for (int i = 0; i < 4; i++)
        outb[(size_t)(n0 + ty + 8 * i) * K + k0 + tx] = __float2half(tile[tx][ty + 8 * i]);
}

// ---------------- kernel: zero counters --------------------------------------
__global__ void moe_zero_cnt_kernel(int* cnt) {
    if (threadIdx.x < E_NUM) cnt[threadIdx.x] = 0;
}

// ---------------- kernel: router + softmax + top4 + gather -------------------
__global__ void moe_router_kernel(const float* __restrict__ x,
                                  const float* __restrict__ wr,
                                  __half* __restrict__ xh,
                                  __half* __restrict__ Xg,
                                  int* __restrict__ cnt,
                                  int* __restrict__ t2s,
                                  float* __restrict__ t2w) {
    __shared__ float xs[H_DIM];
    __shared__ float logits[E_NUM];
    __shared__ int   sel_slot[TOPK];
    __shared__ float sel_w[TOPK];

    const int t = blockIdx.x;
    const int tid = threadIdx.x;
    const int lane = tid & 31;
    const int warp = tid >> 5;

    for (int i = tid; i < H_DIM; i += 128) xs[i] = x[(size_t)t * H_DIM + i];
    __syncthreads();

    for (int e = warp * 4; e < warp * 4 + 4; e++) {
        float s = 0.f;
        const float* wre = wr + (size_t)e * H_DIM;
        for (int h = lane; h < H_DIM; h += 32) s += xs[h] * wre[h];
        #pragma unroll
        for (int off = 16; off; off >>= 1) s += __shfl_xor_sync(0xffffffffu, s, off);
        if (lane == 0) logits[e] = s;
    }
    __syncthreads();

    if (tid == 0) {
        float p[E_NUM];
        float mx = -1e30f;
        #pragma unroll
        for (int e = 0; e < E_NUM; e++) mx = fmaxf(mx, logits[e]);
        #pragma unroll
        for (int e = 0; e < E_NUM; e++) p[e] = expf(logits[e] - mx);
        float tw = 0.f;
        for (int j = 0; j < TOPK; j++) {
            int am = 0; float bv = -1.f;
            #pragma unroll
            for (int e = 0; e < E_NUM; e++) { if (p[e] > bv) { bv = p[e]; am = e; } }
            int pos = atomicAdd(&cnt[am], 1);
            int slot = am * CAP + pos;
            sel_slot[j] = slot;
            sel_w[j]    = bv;
            tw += bv;
            p[am] = -2.f;
        }
        float inv = 1.f / tw;
        for (int j = 0; j < TOPK; j++) {
            float w = sel_w[j] * inv;
            sel_w[j] = w;
            t2s[t * TOPK + j] = sel_slot[j];
            t2w[t * TOPK + j] = w;
        }
    }
    __syncthreads();

    const int s0 = sel_slot[0], s1 = sel_slot[1], s2 = sel_slot[2], s3 = sel_slot[3];
    const float w0 = sel_w[0], w1 = sel_w[1], w2 = sel_w[2], w3 = sel_w[3];
    for (int i = tid; i < H_DIM; i += 128) {
        float v = xs[i];
        xh[(size_t)t * H_DIM + i]  = __float2half(v);
        Xg[(size_t)s0 * H_DIM + i] = __float2half(w0 * v);
        Xg[(size_t)s1 * H_DIM + i] = __float2half(w1 * v);
        Xg[(size_t)s2 * H_DIM + i] = __float2half(w2 * v);
        Xg[(size_t)s3 * H_DIM + i] = __float2half(w3 * v);
    }
}

// ---------------- kernel: fused gate/up GEMM + silu (cp.async 3-stage) -------
// A[m][k] fp16, Bg/Bu transposed [n][k] fp16, C tile 128x64, K = H_DIM.
template <bool ROUTED>
__global__ __launch_bounds__(256)
void moe_gu_kernel(const __half* __restrict__ Abase,
                   const __half* __restrict__ BgT,
                   const __half* __restrict__ BuT,
                   __half* __restrict__ Hbase,
                   const int* __restrict__ cnt,
                   int F) {
    const int e = blockIdx.z;
    int M;
    const __half *A, *Bg, *Bu;
    __half* Hout;
    if (ROUTED) {
        M = cnt[e];
        A    = Abase + (size_t)e * CAP * H_DIM;
        Bg   = BgT   + (size_t)e * H_DIM * F;
        Bu   = BuT   + (size_t)e * H_DIM * F;
        Hout = Hbase + (size_t)e * CAP * F;
    } else {
        M = T_NUM; A = Abase; Bg = BgT; Bu = BuT; Hout = Hbase;
    }
    const int m0 = blockIdx.x * BM;
    if (m0 >= M) return;
    const int n0 = blockIdx.y * BN;

    extern __shared__ __half smem[];
    const int tid = threadIdx.x;
    const int lane = tid & 31;
    const int warp = tid >> 5;
    const int wm = warp >> 1, wn = warp & 1;

    auto load_stage = [&](int s, int k0) {
        __half* As  = smem + s * GU_STAGE_H;
        __half* Bgs = As + A_HALVES;
        __half* Bus = Bgs + B_HALVES;
        int c = tid;
        #pragma unroll
        for (int i = 0; i < 4; i++, c += 256) {
            int row = c >> 3, ch = c & 7;
            cp16z(sptr(As + row * KSTR + ch * 8),
                  A + (size_t)(m0 + row) * H_DIM + k0 + ch * 8, (m0 + row) < M);
        }
        c = tid;
        #pragma unroll
        for (int i = 0; i < 2; i++, c += 256) {
            int row = c >> 3, ch = c & 7;
            size_t off = (size_t)(n0 + row) * H_DIM + k0 + ch * 8;
            cp16(sptr(Bgs + row * KSTR + ch * 8), Bg + off);
            cp16(sptr(Bus + row * KSTR + ch * 8), Bu + off);
        }
    };

    float accg[2][4][4], accu[2][4][4];
    #pragma unroll
    for (int a = 0; a < 2; a++)
        #pragma unroll
        for (int b = 0; b < 4; b++)
            #pragma unroll
            for (int c = 0; c < 4; c++) { accg[a][b][c] = 0.f; accu[a][b][c] = 0.f; }

    const int KT = H_DIM / BK;
    load_stage(0, 0); CP_COMMIT;
    load_stage(1, BK); CP_COMMIT;

    // ldmatrix per-lane addressing
    const int t8 = lane >> 3, r8 = lane & 7;
    const int aRow = wm * 32 + (t8 & 1) * 8 + r8;   // + mf*16
    const int aCol = (t8 >> 1) * 8;                 // + kk
    const int bRow = wn * 32 + (t8 >> 1) * 8 + r8;  // + p*16
    const int bCol = (t8 & 1) * 8;                  // + kk

    for (int it = 0; it < KT; ++it) {
        CP_WAIT1;
        __syncthreads();
        int pf = it + STAGES - 1;
        if (pf < KT) load_stage(pf % STAGES, pf * BK);
        CP_COMMIT;

        const __half* As  = smem + (it % STAGES) * GU_STAGE_H;
        const __half* Bgs = As + A_HALVES;
        const __half* Bus = Bgs + B_HALVES;

        #pragma unroll
        for (int kk = 0; kk < BK; kk += 16) {
            uint32_t a[2][4], bg[2][4], bu[2][4];
            ldm_x4(a[0],  sptr(As  + (aRow)      * KSTR + kk + aCol));
            ldm_x4(a[1],  sptr(As  + (aRow + 16) * KSTR + kk + aCol));
            ldm_x4(bg[0], sptr(Bgs + (bRow)      * KSTR + kk + bCol));
            ldm_x4(bg[1], sptr(Bgs + (bRow + 16) * KSTR + kk + bCol));
            ldm_x4(bu[0], sptr(Bus + (bRow)      * KSTR + kk + bCol));
            ldm_x4(bu[1], sptr(Bus + (bRow + 16) * KSTR + kk + bCol));
            #pragma unroll
            for (int p = 0; p < 2; p++) {
                #pragma unroll
                for (int h = 0; h < 2; h++) {
                    int nf = p * 2 + h;
                    mma16816(accg[0][nf], a[0], &bg[p][h * 2]);
                    mma16816(accg[1][nf], a[1], &bg[p][h * 2]);
                    mma16816(accu[0][nf], a[0], &bu[p][h * 2]);
                    mma16816(accu[1][nf], a[1], &bu[p][h * 2]);
                }
            }
        }
    }

    // epilogue: h = silu(g) * u -> fp16
    #pragma unroll
    for (int mf = 0; mf < 2; mf++) {
        #pragma unroll
        for (int nf = 0; nf < 4; nf++) {
            int row0 = m0 + wm * 32 + mf * 16 + (lane >> 2);
            int col  = n0 + wn * 32 + nf * 8 + (lane & 3) * 2;
            float* g = accg[mf][nf];
            float* u = accu[mf][nf];
            if (row0 < M) {
                float h0 = silu_f(g[0]) * u[0];
                float h1 = silu_f(g[1]) * u[1];
                *(__half2*)&Hout[(size_t)row0 * F + col] = __floats2half2_rn(h0, h1);
            }
            int row1 = row0 + 8;
            if (row1 < M) {
                float h2 = silu_f(g[2]) * u[2];
                float h3 = silu_f(g[3]) * u[3];
                *(__half2*)&Hout[(size_t)row1 * F + col] = __floats2half2_rn(h2, h3);
            }
        }
    }
}

// ---------------- kernel: down GEMM (cp.async 3-stage) -----------------------
// A = h fp16 [m][k], B = WdT [n=H][k] fp16. ROUTED -> Yr slot rows; else -> out.
template <bool ROUTED>
__global__ __launch_bounds__(256)
void moe_down_kernel(const __half* __restrict__ Hbase,
                     const __half* __restrict__ WdTall,
                     float* __restrict__ outDirect,
                     const int* __restrict__ cnt,
                     float* __restrict__ Yr,
                     int K) {
    const int e = blockIdx.z;
    int M;
    const __half *A, *B;
    if (ROUTED) {
        M = cnt[e];
        A = Hbase  + (size_t)e * CAP * K;
        B = WdTall + (size_t)e * (size_t)H_DIM * K;
    } else {
        M = T_NUM; A = Hbase; B = WdTall;
    }
    const int m0 = blockIdx.x * BM;
    if (m0 >= M) return;
    const int n0 = blockIdx.y * BN;

    extern __shared__ __half smem[];
    const int tid = threadIdx.x;
    const int lane = tid & 31;
    const int warp = tid >> 5;
    const int wm = warp >> 1, wn = warp & 1;

    auto load_stage = [&](int s, int k0) {
        __half* As = smem + s * DN_STAGE_H;
        __half* Bs = As + A_HALVES;
        int c = tid;
        #pragma unroll
        for (int i = 0; i < 4; i++, c += 256) {
            int row = c >> 3, ch = c & 7;
            cp16z(sptr(As + row * KSTR + ch * 8),
                  A + (size_t)(m0 + row) * K + k0 + ch * 8, (m0 + row) < M);
        }
        c = tid;
        #pragma unroll
        for (int i = 0; i < 2; i++, c += 256) {
            int row = c >> 3, ch = c & 7;
            cp16(sptr(Bs + row * KSTR + ch * 8),
                 B + (size_t)(n0 + row) * K + k0 + ch * 8);
        }
    };

    float acc[2][4][4];
    #pragma unroll
    for (int a = 0; a < 2; a++)
        #pragma unroll
        for (int b = 0; b < 4; b++)
            #pragma unroll
            for (int c = 0; c < 4; c++) acc[a][b][c] = 0.f;

    const int KT = K / BK;
    load_stage(0, 0); CP_COMMIT;
    load_stage(1, BK); CP_COMMIT;

    const int t8 = lane >> 3, r8 = lane & 7;
    const int aRow = wm * 32 + (t8 & 1) * 8 + r8;
    const int aCol = (t8 >> 1) * 8;
    const int bRow = wn * 32 + (t8 >> 1) * 8 + r8;
    const int bCol = (t8 & 1) * 8;

    for (int it = 0; it < KT; ++it) {
        CP_WAIT1;
        __syncthreads();
        int pf = it + STAGES - 1;
        if (pf < KT) load_stage(pf % STAGES, pf * BK);
        CP_COMMIT;

        const __half* As = smem + (it % STAGES) * DN_STAGE_H;
        const __half* Bs = As + A_HALVES;

        #pragma unroll
        for (int kk = 0; kk < BK; kk += 16) {
            uint32_t a[2][4], b[2][4];
            ldm_x4(a[0], sptr(As + (aRow)      * KSTR + kk + aCol));
            ldm_x4(a[1], sptr(As + (aRow + 16) * KSTR + kk + aCol));
            ldm_x4(b[0], sptr(Bs + (bRow)      * KSTR + kk + bCol));
            ldm_x4(b[1], sptr(Bs + (bRow + 16) * KSTR + kk + bCol));
            #pragma unroll
            for (int p = 0; p < 2; p++) {
                #pragma unroll
                for (int h = 0; h < 2; h++) {
                    int nf = p * 2 + h;
                    mma16816(acc[0][nf], a[0], &b[p][h * 2]);
                    mma16816(acc[1][nf], a[1], &b[p][h * 2]);
                }
            }
        }
    }

    #pragma unroll
    for (int mf = 0; mf < 2; mf++) {
        #pragma unroll
        for (int nf = 0; nf < 4; nf++) {
            int row0 = m0 + wm * 32 + mf * 16 + (lane >> 2);
            int col  = n0 + wn * 32 + nf * 8 + (lane & 3) * 2;
            float* c = acc[mf][nf];
            if (ROUTED) {
                if (row0 < M) {
                    float2 v = {c[0], c[1]};
                    *(float2*)&Yr[(size_t)(e * CAP + row0) * H_DIM + col] = v;
                }
                int row1 = row0 + 8;
                if (row1 < M) {
                    float2 v = {c[2], c[3]};
                    *(float2*)&Yr[(size_t)(e * CAP + row1) * H_DIM + col] = v;
                }
            } else {
                float2 v0 = {c[0], c[1]};
                float2 v1 = {c[2], c[3]};
                *(float2*)&outDirect[(size_t)row0 * H_DIM + col] = v0;
                *(float2*)&outDirect[(size_t)(row0 + 8) * H_DIM + col] = v1;
            }
        }
    }
}

// ---------------- kernel: combine routed contributions -----------------------
__global__ void moe_combine_kernel(float* __restrict__ out,
                                   const float* __restrict__ Yr,
                                   const int* __restrict__ t2s,
                                   const float* __restrict__ t2w) {
    const int t = blockIdx.x;
    const int s0 = t2s[t * TOPK + 0], s1 = t2s[t * TOPK + 1];
    const int s2 = t2s[t * TOPK + 2], s3 = t2s[t * TOPK + 3];
    const float w0 = t2w[t * TOPK + 0], w1 = t2w[t * TOPK + 1];
    const float w2 = t2w[t * TOPK + 2], w3 = t2w[t * TOPK + 3];
    float4* o = (float4*)(out + (size_t)t * H_DIM);
    const float4* y0 = (const float4*)(Yr + (size_t)s0 * H_DIM);
    const float4* y1 = (const float4*)(Yr + (size_t)s1 * H_DIM);
    const float4* y2 = (const float4*)(Yr + (size_t)s2 * H_DIM);
    const float4* y3 = (const float4*)(Yr + (size_t)s3 * H_DIM);
    for (int i = threadIdx.x; i < H_DIM / 4; i += 256) {
        float4 v = o[i];
        float4 a0 = y0[i], a1 = y1[i], a2 = y2[i], a3 = y3[i];
        v.x += w0 * a0.x + w1 * a1.x + w2 * a2.x + w3 * a3.x;
        v.y += w0 * a0.y + w1 * a1.y + w2 * a2.y + w3 * a3.y;
        v.z += w0 * a0.z + w1 * a1.z + w2 * a2.z + w3 * a3.z;
        v.w += w0 * a0.w + w1 * a1.w + w2 * a2.w + w3 * a3.w;
        o[i] = v;
    }
}

// ---------------- launch -----------------------------------------------------
extern "C" void kernel_launch(void* const* d_in, const int* in_sizes, int n_in,
                              void* d_out, int out_size) {
    const float* x   = (const float*)d_in[0];
    const float* wr  = (const float*)d_in[1];
    const float* Wg  = (const float*)d_in[2];
    const float* Wu  = (const float*)d_in[3];
    const float* Wd  = (const float*)d_in[4];
    const float* Wgs = (const float*)d_in[5];
    const float* Wus = (const float*)d_in[6];
    const float* Wds = (const float*)d_in[7];
    float* out = (float*)d_out;

    __half *Xg, *xh, *hr, *hs, *WgT, *WuT, *WdT, *WgsT, *WusT, *WdsT;
    float *Yr, *t2w;
    int *cnt, *t2s;
    cudaGetSymbolAddress((void**)&Xg,   d_Xg);
    cudaGetSymbolAddress((void**)&xh,   d_xh);
    cudaGetSymbolAddress((void**)&hr,   d_hr);
    cudaGetSymbolAddress((void**)&hs,   d_hs);
    cudaGetSymbolAddress((void**)&Yr,   d_Yr);
    cudaGetSymbolAddress((void**)&WgT,  d_WgT);
    cudaGetSymbolAddress((void**)&WuT,  d_WuT);
    cudaGetSymbolAddress((void**)&WdT,  d_WdT);
    cudaGetSymbolAddress((void**)&WgsT, d_WgsT);
    cudaGetSymbolAddress((void**)&WusT, d_WusT);
    cudaGetSymbolAddress((void**)&WdsT, d_WdsT);
    cudaGetSymbolAddress((void**)&cnt,  d_cnt);
    cudaGetSymbolAddress((void**)&t2s,  d_t2s);
    cudaGetSymbolAddress((void**)&t2w,  d_t2w);

    cudaFuncSetAttribute(moe_gu_kernel<true>,  cudaFuncAttributeMaxDynamicSharedMemorySize, GU_SMEM);
    cudaFuncSetAttribute(moe_gu_kernel<false>, cudaFuncAttributeMaxDynamicSharedMemorySize, GU_SMEM);
    cudaFuncSetAttribute(moe_down_kernel<true>,  cudaFuncAttributeMaxDynamicSharedMemorySize, DN_SMEM);
    cudaFuncSetAttribute(moe_down_kernel<false>, cudaFuncAttributeMaxDynamicSharedMemorySize, DN_SMEM);

    dim3 tb(32, 8);
    // Wg/Wu: [e][H][F] -> [e][F][H]
    transpose_f2h_kernel<<<dim3(F_DIM / 32, H_DIM / 32, E_NUM), tb>>>(Wg, WgT, H_DIM, F_DIM);
    transpose_f2h_kernel<<<dim3(F_DIM / 32, H_DIM / 32, E_NUM), tb>>>(Wu, WuT, H_DIM, F_DIM);
    // Wd: [e][F][H] -> [e][H][F]
    transpose_f2h_kernel<<<dim3(H_DIM / 32, F_DIM / 32, E_NUM), tb>>>(Wd, WdT, F_DIM, H_DIM);
    // shared
    transpose_f2h_kernel<<<dim3(FS_DIM / 32, H_DIM / 32, 1), tb>>>(Wgs, WgsT, H_DIM, FS_DIM);
    transpose_f2h_kernel<<<dim3(FS_DIM / 32, H_DIM / 32, 1), tb>>>(Wus, WusT, H_DIM, FS_DIM);
    transpose_f2h_kernel<<<dim3(H_DIM / 32, FS_DIM / 32, 1), tb>>>(Wds, WdsT, FS_DIM, H_DIM);

    moe_zero_cnt_kernel<<<1, 32>>>(cnt);
    moe_router_kernel<<<T_NUM, 128>>>(x, wr, xh, Xg, cnt, t2s, t2w);

    moe_gu_kernel<true><<<dim3(CAP / BM, F_DIM / BN, E_NUM), 256, GU_SMEM>>>(
        Xg, WgT, WuT, hr, cnt, F_DIM);
    moe_gu_kernel<false><<<dim3(T_NUM / BM, FS_DIM / BN, 1), 256, GU_SMEM>>>(
        xh, WgsT, WusT, hs, nullptr, FS_DIM);

    moe_down_kernel<false><<<dim3(T_NUM / BM, H_DIM / BN, 1), 256, DN_SMEM>>>(
        hs, WdsT, out, nullptr, nullptr, FS_DIM);
    moe_down_kernel<true><<<dim3(CAP / BM, H_DIM / BN, E_NUM), 256, DN_SMEM>>>(
        hr, WdT, nullptr, cnt, Yr, F_DIM);

    moe_combine_kernel<<<T_NUM, 256>>>(out, Yr, t2s, t2w);
}